// round 14
// baseline (speedup 1.0000x reference)
#include <cuda_runtime.h>
#include <cstdint>

#define BATCH  8192
#define DCONT  1024
#define VCAT   10000
#define VEC    2500          // float4s per categorical row
#define FULL   0xffffffffu
#define NWARP  4
#define NCHUNK 20            // chunks of 128 vectors per row
#define CAP    640           // 20 ballots * 32 bits = hard max entries per row

// Phase 2: reload recorded groups, rebuild masks, gather W_cat rows in
// parallel across lanes, butterfly-reduce. Returns this lane's output
// quarter (lanes 0-3) and the warp-wide nonzero count in cnt.
__device__ __forceinline__ float4 gather_reduce(const unsigned short* __restrict__ l,
                                                int nE,
                                                const uint4* __restrict__ xr,
                                                const float4* __restrict__ Wcat4,
                                                int lane, int& cnt) {
    float a[16];
    #pragma unroll
    for (int k = 0; k < 16; k++) a[k] = 0.f;
    int cc = 0;

    #pragma unroll 1
    for (int e = lane; e < nE; e += 32) {
        int idx = (int)l[e];                   // vec index of segment 0
        #pragma unroll
        for (int k = 0; k < 4; k++) {          // this lane's 4 recorded vectors
            int vi = idx + 32 * k;
            if (vi < VEC) {
                uint4 v = __ldg(xr + vi);
                unsigned mk = (v.x ? 1u : 0u) | (v.y ? 2u : 0u)
                            | (v.z ? 4u : 0u) | (v.w ? 8u : 0u);
                if (mk) {
                    cc += __popc(mk);
                    int colb = vi * 4;
                    #pragma unroll
                    for (int j = 0; j < 4; j++) {
                        if (mk & (1u << j)) {
                            const float4* w = Wcat4 + (size_t)(colb + j) * 4;
                            float4 t0 = __ldg(w + 0), t1 = __ldg(w + 1);
                            float4 t2 = __ldg(w + 2), t3 = __ldg(w + 3);
                            a[0]+=t0.x;  a[1]+=t0.y;  a[2]+=t0.z;  a[3]+=t0.w;
                            a[4]+=t1.x;  a[5]+=t1.y;  a[6]+=t1.z;  a[7]+=t1.w;
                            a[8]+=t2.x;  a[9]+=t2.y;  a[10]+=t2.z; a[11]+=t2.w;
                            a[12]+=t3.x; a[13]+=t3.y; a[14]+=t3.z; a[15]+=t3.w;
                        }
                    }
                }
            }
        }
    }
    #pragma unroll
    for (int off = 16; off >= 1; off >>= 1) {
        #pragma unroll
        for (int k = 0; k < 16; k++) a[k] += __shfl_xor_sync(FULL, a[k], off);
        cc += __shfl_xor_sync(FULL, cc, off);
    }
    cnt = cc;
    float4 r = make_float4(0.f, 0.f, 0.f, 0.f);
    if      (lane == 0) r = make_float4(a[0],  a[1],  a[2],  a[3]);
    else if (lane == 1) r = make_float4(a[4],  a[5],  a[6],  a[7]);
    else if (lane == 2) r = make_float4(a[8],  a[9],  a[10], a[11]);
    else if (lane == 3) r = make_float4(a[12], a[13], a[14], a[15]);
    return r;
}

__global__ void __launch_bounds__(128, 7)
spfl_kernel(const float* __restrict__ xcont,
            const float* __restrict__ xcat,
            const float* __restrict__ Wc,
            const float* __restrict__ Wcat,
            const float* __restrict__ bias,
            float* __restrict__ out) {
    __shared__ unsigned short lst[NWARP][2][CAP];   // 10 KB/block

    const int wid  = threadIdx.x >> 5;
    const int lane = threadIdx.x & 31;
    const int warp = blockIdx.x * NWARP + wid;
    const int row0 = warp * 2;                 // exact grid: no bounds check
    const unsigned lt = (1u << lane) - 1u;

    const uint4*  __restrict__ xr0   = reinterpret_cast<const uint4*>(xcat) + (size_t)row0 * VEC;
    const uint4*  __restrict__ xr1   = xr0 + VEC;
    const float4* __restrict__ Wcat4 = reinterpret_cast<const float4*>(Wcat);
    const float4* __restrict__ Wc4   = reinterpret_cast<const float4*>(Wc);

    // ========== Phase 1: minimal stream: OR-tree + ballot + rare append =====
    int nE0 = 0, nE1 = 0;
    const uint4 z = make_uint4(0u, 0u, 0u, 0u);

    uint4 a0 = __ldcs(xr0 + lane),      a1 = __ldcs(xr0 + lane + 32);
    uint4 a2 = __ldcs(xr0 + lane + 64), a3 = __ldcs(xr0 + lane + 96);
    uint4 b0 = __ldcs(xr1 + lane),      b1 = __ldcs(xr1 + lane + 32);
    uint4 b2 = __ldcs(xr1 + lane + 64), b3 = __ldcs(xr1 + lane + 96);

    #pragma unroll 1
    for (int c = 0; c < NCHUNK; c++) {
        uint4 n0 = z, n1 = z, n2 = z, n3 = z;
        uint4 p0 = z, p1 = z, p2 = z, p3 = z;
        if (c < 18) {                          // full prefetch of chunk c+1
            const uint4* q0 = xr0 + (c + 1) * 128 + lane;
            const uint4* q1 = xr1 + (c + 1) * 128 + lane;
            n0 = __ldcs(q0); n1 = __ldcs(q0 + 32); n2 = __ldcs(q0 + 64); n3 = __ldcs(q0 + 96);
            p0 = __ldcs(q1); p1 = __ldcs(q1 + 32); p2 = __ldcs(q1 + 64); p3 = __ldcs(q1 + 96);
        } else if (c == 18) {                  // partial tail chunk 19
            int b = 19 * 128 + lane;
            n0 = __ldcs(xr0 + b);      p0 = __ldcs(xr1 + b);          // < 2500
            n1 = __ldcs(xr0 + b + 32); p1 = __ldcs(xr1 + b + 32);     // < 2500
            if (b + 64 < VEC) { n2 = __ldcs(xr0 + b + 64); p2 = __ldcs(xr1 + b + 64); }
        }

        unsigned vid = (unsigned)(c * 128 + lane);

        unsigned o0 = ((a0.x | a0.y) | (a0.z | a0.w)) | ((a1.x | a1.y) | (a1.z | a1.w))
                    | ((a2.x | a2.y) | (a2.z | a2.w)) | ((a3.x | a3.y) | (a3.z | a3.w));
        unsigned bal0 = __ballot_sync(FULL, o0 != 0u);
        if (o0) lst[wid][0][nE0 + __popc(bal0 & lt)] = (unsigned short)vid;
        nE0 += __popc(bal0);

        unsigned o1 = ((b0.x | b0.y) | (b0.z | b0.w)) | ((b1.x | b1.y) | (b1.z | b1.w))
                    | ((b2.x | b2.y) | (b2.z | b2.w)) | ((b3.x | b3.y) | (b3.z | b3.w));
        unsigned bal1 = __ballot_sync(FULL, o1 != 0u);
        if (o1) lst[wid][1][nE1 + __popc(bal1 & lt)] = (unsigned short)vid;
        nE1 += __popc(bal1);

        a0 = n0; a1 = n1; a2 = n2; a3 = n3;
        b0 = p0; b1 = p1; b2 = p2; b3 = p3;
    }

    __syncwarp();

    // ========== Phase 2: reload recorded groups, gather + reduce ============
    int cnt0, cnt1;
    float4 acc0 = gather_reduce(&lst[wid][0][0], nE0, xr0, Wcat4, lane, cnt0);
    float4 acc1 = gather_reduce(&lst[wid][1][0], nE1, xr1, Wcat4, lane, cnt1);

    // ========== Continuous branch: proven c/g layout ========================
    const int g  = lane >> 2;
    const int c4 = lane & 3;
    const float* __restrict__ xc0 = xcont + (size_t)row0 * DCONT;
    const float* __restrict__ xc1 = xc0 + DCONT;
    #pragma unroll 1
    for (int jb = 0; jb < DCONT; jb += 32) {
        float x0 = __ldg(xc0 + jb + lane);
        float x1 = __ldg(xc1 + jb + lane);
        #pragma unroll
        for (int s = 0; s < 4; s++) {
            int jl = s * 8 + g;
            float4 w = __ldg(Wc4 + (size_t)(jb + jl) * 4 + c4);
            float v0 = __shfl_sync(FULL, x0, jl);
            float v1 = __shfl_sync(FULL, x1, jl);
            acc0.x += v0 * w.x; acc0.y += v0 * w.y; acc0.z += v0 * w.z; acc0.w += v0 * w.w;
            acc1.x += v1 * w.x; acc1.y += v1 * w.y; acc1.z += v1 * w.z; acc1.w += v1 * w.w;
        }
    }

    // ---- reduce cont partials over g (cat quarters ride in g==0 lanes) ----
    #pragma unroll
    for (int off = 4; off <= 16; off <<= 1) {
        acc0.x += __shfl_xor_sync(FULL, acc0.x, off);
        acc0.y += __shfl_xor_sync(FULL, acc0.y, off);
        acc0.z += __shfl_xor_sync(FULL, acc0.z, off);
        acc0.w += __shfl_xor_sync(FULL, acc0.w, off);
        acc1.x += __shfl_xor_sync(FULL, acc1.x, off);
        acc1.y += __shfl_xor_sync(FULL, acc1.y, off);
        acc1.z += __shfl_xor_sync(FULL, acc1.z, off);
        acc1.w += __shfl_xor_sync(FULL, acc1.w, off);
    }

    if (lane < 4) {   // g==0, quarter c4 == lane
        float4 b4 = __ldg(reinterpret_cast<const float4*>(bias) + lane);
        float f0 = (float)(DCONT + cnt0);
        float f1 = (float)(DCONT + cnt1);
        float4 o0, o1;
        o0.x = acc0.x + f0 * b4.x; o0.y = acc0.y + f0 * b4.y;
        o0.z = acc0.z + f0 * b4.z; o0.w = acc0.w + f0 * b4.w;
        o1.x = acc1.x + f1 * b4.x; o1.y = acc1.y + f1 * b4.y;
        o1.z = acc1.z + f1 * b4.z; o1.w = acc1.w + f1 * b4.w;
        reinterpret_cast<float4*>(out)[(size_t)row0 * 4 + lane]       = o0;
        reinterpret_cast<float4*>(out)[(size_t)(row0 + 1) * 4 + lane] = o1;
    }
}

extern "C" void kernel_launch(void* const* d_in, const int* in_sizes, int n_in,
                              void* d_out, int out_size) {
    const float* xcont = (const float*)d_in[0];   // [8192, 1024]
    const float* xcat  = (const float*)d_in[1];   // [8192, 10000]
    const float* Wc    = (const float*)d_in[2];   // [1024, 16]
    const float* Wcat  = (const float*)d_in[3];   // [10000, 16]
    const float* bias  = (const float*)d_in[4];   // [16]
    float* out = (float*)d_out;                   // [8192, 16]

    // 2 rows per warp, 4 warps per block -> 1024 blocks (single wave)
    dim3 grid(BATCH / (2 * NWARP));
    dim3 block(32 * NWARP);
    spfl_kernel<<<grid, block>>>(xcont, xcat, Wc, Wcat, bias, out);
}